// round 15
// baseline (speedup 1.0000x reference)
#include <cuda_runtime.h>
#include <cuda_fp16.h>
#include <math.h>
#include <stdint.h>

#define BATCH 32768
#define NT 512
#define WTOT 1085600
#define ASTRB 80          // smem row stride in bytes (40 halves)
#define A_SZ 10240        // one A split-term tile: 128*80
#define B_SZ 10240        // one B split-term tile: 128*80
#define STG 40960         // stage: 2*A_SZ + 2*B_SZ
#define DYN_BYTES (2 * STG)

typedef unsigned int u32;

// ---------------- scratch (device globals) ----------------
__device__ __half g_xh[2][(size_t)BATCH * 24];
__device__ __half g_c1h[2][(size_t)BATCH * 304];
__device__ __half g_c2h[2][(size_t)BATCH * 600];
__device__ __half g_c3h[2][(size_t)BATCH * 600];
__device__ __half g_r150[2][(size_t)BATCH * 152];
__device__ __half g_r50[2][(size_t)BATCH * 56];
__device__ __half g_r300[2][(size_t)BATCH * 304];
__device__ __half g_r100[2][(size_t)BATCH * 104];
__device__ __half g_wh[2][WTOT];
__device__ double g_stats[3][2];
__device__ float g_ws[1712];

// ---------------- asm helpers ----------------
__device__ __forceinline__ void cpa16(u32 dst, const void *src, int sb) {
    asm volatile("cp.async.cg.shared.global [%0], [%1], 16, %2;\n"
                 :: "r"(dst), "l"(src), "r"(sb));
}
__device__ __forceinline__ void cp_commitg() { asm volatile("cp.async.commit_group;\n" ::: "memory"); }
__device__ __forceinline__ void cp_wait0() { asm volatile("cp.async.wait_group 0;\n" ::: "memory"); }

__device__ __forceinline__ void ldsm4(u32 &r0, u32 &r1, u32 &r2, u32 &r3, u32 a) {
    asm volatile("ldmatrix.sync.aligned.m8n8.x4.shared.b16 {%0,%1,%2,%3}, [%4];"
                 : "=r"(r0), "=r"(r1), "=r"(r2), "=r"(r3) : "r"(a));
}
__device__ __forceinline__ void mma16816(float *c, const u32 *a, const u32 *b) {
    asm volatile("mma.sync.aligned.m16n8k16.row.col.f32.f16.f16.f32 "
                 "{%0,%1,%2,%3}, {%4,%5,%6,%7}, {%8,%9}, {%0,%1,%2,%3};"
                 : "+f"(c[0]), "+f"(c[1]), "+f"(c[2]), "+f"(c[3])
                 : "r"(a[0]), "r"(a[1]), "r"(a[2]), "r"(a[3]), "r"(b[0]), "r"(b[1]));
}
// fast mish for v >= 0: mish(v) = v * (1 - 2/(u^2 + 2u + 2)), u = e^v
__device__ __forceinline__ float mishf(float v) {
    float u = __expf(v);
    float d = fmaf(u, u + 2.f, 2.f);
    return v * (1.f - __fdividef(2.f, d));
}
__device__ __forceinline__ float sigf(float v) {
    return __fdividef(1.f, 1.f + __expf(-v));
}
__device__ __forceinline__ void bn_affine(int p, const float *g, const float *b,
                                          double cnt, float *o2) {
    double mean = g_stats[p][0] / cnt;
    double var = g_stats[p][1] / cnt - mean * mean;
    double al = (double)g[0] / sqrt(var + 1e-5);
    o2[0] = (float)al;
    o2[1] = (float)((double)b[0] - mean * al);
}
// paired split-store: two adjacent columns -> two half2 stores (term1, term2)
__device__ __forceinline__ void sst2h(__half *base, size_t vs, size_t off, float a, float c) {
    __half a1 = __float2half_rn(a), c1 = __float2half_rn(c);
    __half a2 = __float2half_rn(a - __half2float(a1));
    __half c2 = __float2half_rn(c - __half2float(c1));
    *(__half2 *)(base + off) = __halves2half2(a1, c1);
    *(__half2 *)(base + vs + off) = __halves2half2(a2, c2);
}
__device__ __forceinline__ int clampi(int v, int lo, int hi) {
    return v < lo ? lo : (v > hi ? hi : v);
}

// ---------------- setup: zero stats + weight rowsums ----------------
__global__ void setup_kernel(const float *__restrict__ w3, const float *__restrict__ w6,
                             const float *__restrict__ wfc) {
    int b = blockIdx.x;
    if (b == 0 && threadIdx.x < 6) ((double *)g_stats)[threadIdx.x] = 0.0;
    const float *src; int K;
    if (b < 600)       { src = w3 + (size_t)b * 300;          K = 300; }
    else if (b < 1200) { src = w6 + (size_t)(b - 600) * 600;  K = 600; }
    else               { src = wfc + (size_t)(b - 1200) * 600; K = 600; }
    float s = 0.f;
    for (int k = threadIdx.x; k < K; k += 128) s += src[k];
#pragma unroll
    for (int o = 16; o; o >>= 1) s += __shfl_down_sync(0xffffffffu, s, o);
    __shared__ float sm[4];
    if ((threadIdx.x & 31) == 0) sm[threadIdx.x >> 5] = s;
    __syncthreads();
    if (threadIdx.x == 0) g_ws[b] = sm[0] + sm[1] + sm[2] + sm[3];
}

// ---------------- split kernels (fp16 x2) ----------------
struct WL { const float *src; int K; int rows; int dstride; size_t doff; };
struct WT { WL l[10]; };

__global__ void splitw_kernel(WT wt) {
    int b = blockIdx.x, li = 0;
    while (b >= wt.l[li].rows) { b -= wt.l[li].rows; ++li; }
    WL L = wt.l[li];
    const float *src = L.src + (size_t)b * L.K;
    __half *d0 = &g_wh[0][L.doff + (size_t)b * L.dstride];
    for (int k = threadIdx.x; k < L.K; k += 128) {
        float w = src[k];
        __half h1 = __float2half_rn(w);
        __half h2 = __float2half_rn(w - __half2float(h1));
        d0[k] = h1; d0[WTOT + k] = h2;
    }
}

__global__ void splitx_kernel(const float *__restrict__ x) {
    int i = blockIdx.x * blockDim.x + threadIdx.x;
    if (i < BATCH * 24) {
        float w = x[i];
        __half h1 = __float2half_rn(w);
        __half h2 = __float2half_rn(w - __half2float(h1));
        g_xh[0][i] = h1; g_xh[1][i] = h2;
    }
}

// ---------------- HMMA GEMM (fp16x2 split, 3 products, 128x128 tile) --------------
template <int FC>
__global__ __launch_bounds__(NT, 1) void gemm_hmma(
    const __half *__restrict__ A, size_t avs, int lda,
    const __half *__restrict__ W, int ldw,
    const float *__restrict__ bias, const float *__restrict__ wsum,
    int K, int N, int OUT,
    __half *__restrict__ col, size_t cvs, int ldc,
    __half *__restrict__ car, size_t crvs, int ldcar,
    int sphase, int aphase,
    const float *__restrict__ bng, const float *__restrict__ bnb, double acnt,
    const float *__restrict__ codebook, float *__restrict__ out) {
    extern __shared__ __align__(16) char dyn[];
    __shared__ float saff[2];
    __shared__ float effb[128];
    __shared__ float red[32];
    __shared__ float cbs[128 * 8];

    const int t = threadIdx.x;
    const int wid = t >> 5;
    const int lane = t & 31;
    const int rowBase = blockIdx.y * 128;
    const int colBase = blockIdx.x * 128;

    if (t == 0) {
        if (aphase >= 0) bn_affine(aphase, bng, bnb, acnt, saff);
        else { saff[0] = 1.f; saff[1] = 0.f; }
    }
    if (FC) {
        for (int i = t; i < 128 * 8; i += NT) cbs[i] = codebook[colBase * 8 + i];
    }

    const u32 sb = (u32)__cvta_generic_to_shared(dyn);

    // loader mapping: 512 threads; each thread owns one (row, 16B chunk) pair
    const int arow = t >> 2;            // 0..127
    const int ch = t & 3;               // 16B chunk within 64B K-slab
    const int n_b = colBase + arow;
    const bool bv = n_b < N;

    auto issue = [&](int kt, int buf) {
        const u32 stage = sb + buf * STG;
        int k0 = kt + ch * 8;
        int sbvA = clampi((K - k0) * 2, 0, 16);
        int sbvB = bv ? sbvA : 0;
#pragma unroll
        for (int arr = 0; arr < 2; ++arr) {
            const void *srcA = sbvA > 0
                ? (const void *)(A + (size_t)arr * avs + (size_t)(rowBase + arow) * lda + k0)
                : (const void *)A;
            cpa16(stage + arr * A_SZ + arow * ASTRB + ch * 16, srcA, sbvA);
            const void *srcB = sbvB > 0
                ? (const void *)(W + (size_t)arr * WTOT + (size_t)(bv ? n_b : 0) * ldw + k0)
                : (const void *)A;
            cpa16(stage + 2 * A_SZ + arr * B_SZ + arow * ASTRB + ch * 16, srcB, sbvB);
        }
        cp_commitg();
    };

    float acc[2][4][4];
#pragma unroll
    for (int m = 0; m < 2; m++)
#pragma unroll
        for (int n = 0; n < 4; n++)
#pragma unroll
            for (int v = 0; v < 4; v++) acc[m][n][v] = 0.f;

    const int wr = wid >> 2;            // m block 0..3 (32 rows each)
    const int wc = wid & 3;             // n block 0..3 (32 cols each)
    const int al = lane & 15, ah = lane >> 4;
    const int b7 = lane & 7, bg = (lane >> 4) & 1, bh = (lane >> 3) & 1;

    const int T = (K + 31) >> 5;
    issue(0, 0);
    for (int it = 0; it < T; ++it) {
        cp_wait0();
        __syncthreads();
        if (it + 1 < T) issue((it + 1) * 32, (it + 1) & 1);
        const u32 stage = sb + (it & 1) * STG;
        const u32 Ab = stage;
        const u32 Bb = stage + 2 * A_SZ;
#pragma unroll
        for (int ks = 0; ks < 2; ++ks) {
            u32 a1f[2][4], a2f[2][4];
#pragma unroll
            for (int mt = 0; mt < 2; ++mt) {
                u32 ra = Ab + (wr * 32 + mt * 16 + al) * ASTRB + ks * 32 + ah * 16;
                ldsm4(a1f[mt][0], a1f[mt][1], a1f[mt][2], a1f[mt][3], ra);
                ldsm4(a2f[mt][0], a2f[mt][1], a2f[mt][2], a2f[mt][3], ra + A_SZ);
            }
            u32 b1f[4][2], b2f[4][2];
#pragma unroll
            for (int g = 0; g < 2; ++g) {
                int rrow = wc * 32 + g * 16 + bg * 8 + b7;
                u32 rb = Bb + rrow * ASTRB + ks * 32 + bh * 16;
                u32 r0, r1, r2, r3;
                ldsm4(r0, r1, r2, r3, rb);
                b1f[2 * g][0] = r0; b1f[2 * g][1] = r1;
                b1f[2 * g + 1][0] = r2; b1f[2 * g + 1][1] = r3;
                ldsm4(r0, r1, r2, r3, rb + B_SZ);
                b2f[2 * g][0] = r0; b2f[2 * g][1] = r1;
                b2f[2 * g + 1][0] = r2; b2f[2 * g + 1][1] = r3;
            }
#pragma unroll
            for (int mt = 0; mt < 2; ++mt)
#pragma unroll
                for (int nt = 0; nt < 4; ++nt) {
                    mma16816(acc[mt][nt], a1f[mt], b1f[nt]);
                    mma16816(acc[mt][nt], a1f[mt], b2f[nt]);
                    mma16816(acc[mt][nt], a2f[mt], b1f[nt]);
                }
        }
    }

    // ---- epilogue ----
    const float alpha = saff[0], beta = saff[1];
    if (t < 128) {
        int n = colBase + t;
        effb[t] = (n < N) ? (bias[n] + (wsum ? beta * wsum[n] : 0.f)) : 0.f;
    }
    __syncthreads();

    const int q = lane & 3, lr8 = lane >> 2;
    float lsum = 0.f, lsq = 0.f;
    const size_t seg = (size_t)BATCH * 512;
#pragma unroll
    for (int mt = 0; mt < 2; ++mt)
#pragma unroll
        for (int hr = 0; hr < 2; ++hr) {
            int r = rowBase + wr * 32 + mt * 16 + hr * 8 + lr8;
#pragma unroll
            for (int nt = 0; nt < 4; ++nt) {
                int ln = wc * 32 + nt * 8 + 2 * q;
                int n0 = colBase + ln;
                if (n0 >= N) continue;
                float v0 = fmaf(alpha, acc[mt][nt][hr * 2 + 0], effb[ln]);
                float v1 = fmaf(alpha, acc[mt][nt][hr * 2 + 1], effb[ln + 1]);
                if (FC) {
                    float o0 = sigf(v0);
                    float o1 = sigf(v1);
                    float q0 = -3.4e38f, q1 = -3.4e38f, m0 = 3.4e38f, m1 = 3.4e38f;
                    const float *cb0 = &cbs[ln * 8];
#pragma unroll
                    for (int e = 0; e < 8; e++) {
                        float c0 = cb0[e], c1 = cb0[8 + e];
                        float d0 = (o0 - c0) * (o0 - c0), d1 = (o1 - c1) * (o1 - c1);
                        if (d0 < m0) { m0 = d0; q0 = c0; } else if (d0 == m0) q0 = fmaxf(q0, c0);
                        if (d1 < m1) { m1 = d1; q1 = c1; } else if (d1 == m1) q1 = fmaxf(q1, c1);
                    }
                    size_t idx = (size_t)r * 512 + n0;
                    *(float2 *)(out + idx) = make_float2(o0 + (q0 - o0), o1 + (q1 - o1));
                    *(float2 *)(out + seg + idx) = make_float2(q0, q1);
                    *(float2 *)(out + 2 * seg + idx) = make_float2(o0, o1);
                } else {
                    v0 = fmaxf(v0, 0.f); v1 = fmaxf(v1, 0.f);
                    if (n0 < OUT) {
                        float m0 = mishf(v0), m1 = mishf(v1);
                        lsum += m0 + m1;
                        lsq = fmaf(m0, m0, fmaf(m1, m1, lsq));
                        sst2h(col, cvs, (size_t)r * ldc + n0, m0, m1);
                    } else {
                        sst2h(car, crvs, (size_t)r * ldcar + (n0 - OUT), v0, v1);
                    }
                }
            }
        }

    if (!FC) {
#pragma unroll
        for (int o = 16; o; o >>= 1) {
            lsum += __shfl_down_sync(0xffffffffu, lsum, o);
            lsq += __shfl_down_sync(0xffffffffu, lsq, o);
        }
        if (lane == 0) { red[wid] = lsum; red[16 + wid] = lsq; }
        __syncthreads();
        if (t == 0) {
            float s = 0.f, qq = 0.f;
#pragma unroll
            for (int w = 0; w < 16; w++) { s += red[w]; qq += red[16 + w]; }
            atomicAdd(&g_stats[sphase][0], (double)s);
            atomicAdd(&g_stats[sphase][1], (double)qq);
        }
    }
}

// ---------------- launch ----------------
extern "C" void kernel_launch(void *const *d_in, const int *in_sizes, int n_in,
                              void *d_out, int out_size) {
    (void)in_sizes; (void)n_in; (void)out_size;
    const float *x = (const float *)d_in[0];
    const float *w[9], *bb[9];
    for (int i = 0; i < 9; i++) {
        w[i] = (const float *)d_in[1 + 2 * i];
        bb[i] = (const float *)d_in[2 + 2 * i];
    }
    const float *bn_g[3] = {(const float *)d_in[19], (const float *)d_in[21], (const float *)d_in[23]};
    const float *bn_b[3] = {(const float *)d_in[20], (const float *)d_in[22], (const float *)d_in[24]};
    const float *fc_w = (const float *)d_in[25];
    const float *fc_b = (const float *)d_in[26];
    const float *cbk = (const float *)d_in[27];
    float *out = (float *)d_out;

    __half *xh, *c1, *c2, *c3, *r150, *r50, *r300, *r100, *wh;
    float *wsum;
    cudaGetSymbolAddress((void **)&xh, g_xh);
    cudaGetSymbolAddress((void **)&c1, g_c1h);
    cudaGetSymbolAddress((void **)&c2, g_c2h);
    cudaGetSymbolAddress((void **)&c3, g_c3h);
    cudaGetSymbolAddress((void **)&r150, g_r150);
    cudaGetSymbolAddress((void **)&r50, g_r50);
    cudaGetSymbolAddress((void **)&r300, g_r300);
    cudaGetSymbolAddress((void **)&r100, g_r100);
    cudaGetSymbolAddress((void **)&wh, g_wh);
    cudaGetSymbolAddress((void **)&wsum, g_ws);

    static int attr_done = 0;
    if (!attr_done) {
        cudaFuncSetAttribute(gemm_hmma<0>, cudaFuncAttributeMaxDynamicSharedMemorySize, DYN_BYTES);
        cudaFuncSetAttribute(gemm_hmma<1>, cudaFuncAttributeMaxDynamicSharedMemorySize, DYN_BYTES);
        attr_done = 1;
    }

    const size_t XS = (size_t)BATCH * 24;
    const size_t C1S = (size_t)BATCH * 304, C6S = (size_t)BATCH * 600;
    const size_t S150 = (size_t)BATCH * 152, S50 = (size_t)BATCH * 56;
    const size_t S300 = (size_t)BATCH * 304, S100 = (size_t)BATCH * 104;
    const double cnt1 = (double)BATCH * 300.0, cnt2 = (double)BATCH * 600.0;

    setup_kernel<<<1712, 128>>>(w[3], w[6], fc_w);
    splitx_kernel<<<(BATCH * 24 + 255) / 256, 256>>>(x);
    WT wt;
    wt.l[0] = {w[0], 24, 300, 24, 0};
    wt.l[1] = {w[1], 150, 150, 152, 7200};
    wt.l[2] = {w[2], 50, 50, 56, 30000};
    wt.l[3] = {w[3], 300, 600, 304, 32800};
    wt.l[4] = {w[4], 300, 300, 304, 215200};
    wt.l[5] = {w[5], 100, 100, 104, 306400};
    wt.l[6] = {w[6], 600, 600, 600, 316800};
    wt.l[7] = {w[7], 300, 300, 304, 676800};
    wt.l[8] = {w[8], 100, 100, 104, 768000};
    wt.l[9] = {fc_w, 600, 512, 600, 778400};
    splitw_kernel<<<3012, 128>>>(wt);

    auto G = [](int N) { return dim3((N + 127) / 128, BATCH / 128); };

    // phase 1: 24 -> 300(out150) -> 150(out100) -> 50(out50)
    gemm_hmma<0><<<G(300), NT, DYN_BYTES>>>(xh, XS, 24, wh + 0, 24, bb[0], nullptr,
        24, 300, 150, c1, C1S, 304, r150, S150, 152, 0, -1, nullptr, nullptr, 0.0, nullptr, nullptr);
    gemm_hmma<0><<<G(150), NT, DYN_BYTES>>>(r150, S150, 152, wh + 7200, 152, bb[1], nullptr,
        150, 150, 100, c1 + 150, C1S, 304, r50, S50, 56, 0, -1, nullptr, nullptr, 0.0, nullptr, nullptr);
    gemm_hmma<0><<<G(50), NT, DYN_BYTES>>>(r50, S50, 56, wh + 30000, 56, bb[2], nullptr,
        50, 50, 50, c1 + 250, C1S, 304, r50, S50, 56, 0, -1, nullptr, nullptr, 0.0, nullptr, nullptr);
    // phase 2 (BN1 folded)
    gemm_hmma<0><<<G(600), NT, DYN_BYTES>>>(c1, C1S, 304, wh + 32800, 304, bb[3], wsum,
        300, 600, 300, c2, C6S, 600, r300, S300, 304, 1, 0, bn_g[0], bn_b[0], cnt1, nullptr, nullptr);
    gemm_hmma<0><<<G(300), NT, DYN_BYTES>>>(r300, S300, 304, wh + 215200, 304, bb[4], nullptr,
        300, 300, 200, c2 + 300, C6S, 600, r100, S100, 104, 1, -1, nullptr, nullptr, 0.0, nullptr, nullptr);
    gemm_hmma<0><<<G(100), NT, DYN_BYTES>>>(r100, S100, 104, wh + 306400, 104, bb[5], nullptr,
        100, 100, 100, c2 + 500, C6S, 600, r100, S100, 104, 1, -1, nullptr, nullptr, 0.0, nullptr, nullptr);
    // phase 3 (BN2 folded)
    gemm_hmma<0><<<G(600), NT, DYN_BYTES>>>(c2, C6S, 600, wh + 316800, 600, bb[6], wsum + 600,
        600, 600, 300, c3, C6S, 600, r300, S300, 304, 2, 1, bn_g[1], bn_b[1], cnt2, nullptr, nullptr);
    gemm_hmma<0><<<G(300), NT, DYN_BYTES>>>(r300, S300, 304, wh + 676800, 304, bb[7], nullptr,
        300, 300, 200, c3 + 300, C6S, 600, r100, S100, 104, 2, -1, nullptr, nullptr, 0.0, nullptr, nullptr);
    gemm_hmma<0><<<G(100), NT, DYN_BYTES>>>(r100, S100, 104, wh + 768000, 104, bb[8], nullptr,
        100, 100, 100, c3 + 500, C6S, 600, r100, S100, 104, 2, -1, nullptr, nullptr, 0.0, nullptr, nullptr);
    // fc + sigmoid + codebook (BN3 folded)
    gemm_hmma<1><<<G(512), NT, DYN_BYTES>>>(c3, C6S, 600, wh + 778400, 600, fc_b, wsum + 1200,
        600, 512, 512, nullptr, 0, 0, nullptr, 0, 0, 0, 2, bn_g[2], bn_b[2], cnt2, cbk, out);
}

// round 17
// speedup vs baseline: 1.1322x; 1.1322x over previous
#include <cuda_runtime.h>
#include <cuda_fp16.h>
#include <math.h>
#include <stdint.h>

#define BATCH 32768
#define NT 256
#define WTOT 1085600
#define ASTRB 80          // smem row stride in bytes (40 halves)
#define A_SZ 10240        // one A split-term tile: 128*80
#define B_SZ 5120         // one B split-term tile: 64*80
#define STG 30720         // stage: 2*A_SZ + 2*B_SZ
#define DYN_BYTES (2 * STG)

typedef unsigned int u32;

// ---------------- scratch (device globals) ----------------
__device__ __half g_xh[2][(size_t)BATCH * 24];
__device__ __half g_c1h[2][(size_t)BATCH * 304];
__device__ __half g_c2h[2][(size_t)BATCH * 600];
__device__ __half g_c3h[2][(size_t)BATCH * 600];
__device__ __half g_r150[2][(size_t)BATCH * 152];
__device__ __half g_r50[2][(size_t)BATCH * 56];
__device__ __half g_r300[2][(size_t)BATCH * 304];
__device__ __half g_r100[2][(size_t)BATCH * 104];
__device__ __half g_wh[2][WTOT];
__device__ double g_stats[3][2];
__device__ float g_ws[1712];

// ---------------- asm helpers ----------------
__device__ __forceinline__ void cpa16(u32 dst, const void *src, int sb) {
    asm volatile("cp.async.cg.shared.global [%0], [%1], 16, %2;\n"
                 :: "r"(dst), "l"(src), "r"(sb));
}
__device__ __forceinline__ void cp_commitg() { asm volatile("cp.async.commit_group;\n" ::: "memory"); }
__device__ __forceinline__ void cp_wait0() { asm volatile("cp.async.wait_group 0;\n" ::: "memory"); }

__device__ __forceinline__ void ldsm4(u32 &r0, u32 &r1, u32 &r2, u32 &r3, u32 a) {
    asm volatile("ldmatrix.sync.aligned.m8n8.x4.shared.b16 {%0,%1,%2,%3}, [%4];"
                 : "=r"(r0), "=r"(r1), "=r"(r2), "=r"(r3) : "r"(a));
}
__device__ __forceinline__ void mma16816(float *c, const u32 *a, const u32 *b) {
    asm volatile("mma.sync.aligned.m16n8k16.row.col.f32.f16.f16.f32 "
                 "{%0,%1,%2,%3}, {%4,%5,%6,%7}, {%8,%9}, {%0,%1,%2,%3};"
                 : "+f"(c[0]), "+f"(c[1]), "+f"(c[2]), "+f"(c[3])
                 : "r"(a[0]), "r"(a[1]), "r"(a[2]), "r"(a[3]), "r"(b[0]), "r"(b[1]));
}
// fast mish for v >= 0: mish(v) = v * (1 - 2/(u^2 + 2u + 2)), u = e^v
__device__ __forceinline__ float mishf(float v) {
    float u = __expf(v);
    float d = fmaf(u, u + 2.f, 2.f);
    return v * (1.f - __fdividef(2.f, d));
}
__device__ __forceinline__ float sigf(float v) {
    return __fdividef(1.f, 1.f + __expf(-v));
}
__device__ __forceinline__ void bn_affine(int p, const float *g, const float *b,
                                          double cnt, float *o2) {
    double mean = g_stats[p][0] / cnt;
    double var = g_stats[p][1] / cnt - mean * mean;
    double al = (double)g[0] / sqrt(var + 1e-5);
    o2[0] = (float)al;
    o2[1] = (float)((double)b[0] - mean * al);
}
// paired split-store: two adjacent columns -> two half2 stores (term1, term2)
__device__ __forceinline__ void sst2h(__half *base, size_t vs, size_t off, float a, float c) {
    __half a1 = __float2half_rn(a), c1 = __float2half_rn(c);
    __half a2 = __float2half_rn(a - __half2float(a1));
    __half c2 = __float2half_rn(c - __half2float(c1));
    *(__half2 *)(base + off) = __halves2half2(a1, c1);
    *(__half2 *)(base + vs + off) = __halves2half2(a2, c2);
}
__device__ __forceinline__ int clampi(int v, int lo, int hi) {
    return v < lo ? lo : (v > hi ? hi : v);
}

// ---------------- setup: zero stats + weight rowsums ----------------
__global__ void setup_kernel(const float *__restrict__ w3, const float *__restrict__ w6,
                             const float *__restrict__ wfc) {
    int b = blockIdx.x;
    if (b == 0 && threadIdx.x < 6) ((double *)g_stats)[threadIdx.x] = 0.0;
    const float *src; int K;
    if (b < 600)       { src = w3 + (size_t)b * 300;          K = 300; }
    else if (b < 1200) { src = w6 + (size_t)(b - 600) * 600;  K = 600; }
    else               { src = wfc + (size_t)(b - 1200) * 600; K = 600; }
    float s = 0.f;
    for (int k = threadIdx.x; k < K; k += 128) s += src[k];
#pragma unroll
    for (int o = 16; o; o >>= 1) s += __shfl_down_sync(0xffffffffu, s, o);
    __shared__ float sm[4];
    if ((threadIdx.x & 31) == 0) sm[threadIdx.x >> 5] = s;
    __syncthreads();
    if (threadIdx.x == 0) g_ws[b] = sm[0] + sm[1] + sm[2] + sm[3];
}

// ---------------- split kernels (fp16 x2) ----------------
struct WL { const float *src; int K; int rows; int dstride; size_t doff; };
struct WT { WL l[10]; };

__global__ void splitw_kernel(WT wt) {
    int b = blockIdx.x, li = 0;
    while (b >= wt.l[li].rows) { b -= wt.l[li].rows; ++li; }
    WL L = wt.l[li];
    const float *src = L.src + (size_t)b * L.K;
    __half *d0 = &g_wh[0][L.doff + (size_t)b * L.dstride];
    for (int k = threadIdx.x; k < L.K; k += 128) {
        float w = src[k];
        __half h1 = __float2half_rn(w);
        __half h2 = __float2half_rn(w - __half2float(h1));
        d0[k] = h1; d0[WTOT + k] = h2;
    }
}

__global__ void splitx_kernel(const float *__restrict__ x) {
    int i = blockIdx.x * blockDim.x + threadIdx.x;
    if (i < BATCH * 24) {
        float w = x[i];
        __half h1 = __float2half_rn(w);
        __half h2 = __float2half_rn(w - __half2float(h1));
        g_xh[0][i] = h1; g_xh[1][i] = h2;
    }
}

// ---------------- HMMA GEMM (fp16x2 split, 3 products) + fused epilogue ----------------
template <int FC>
__global__ __launch_bounds__(NT, 3) void gemm_hmma(
    const __half *__restrict__ A, size_t avs, int lda,
    const __half *__restrict__ W, int ldw,
    const float *__restrict__ bias, const float *__restrict__ wsum,
    int K, int N, int OUT,
    __half *__restrict__ col, size_t cvs, int ldc,
    __half *__restrict__ car, size_t crvs, int ldcar,
    int sphase, int aphase,
    const float *__restrict__ bng, const float *__restrict__ bnb, double acnt,
    const float *__restrict__ codebook, float *__restrict__ out) {
    extern __shared__ __align__(16) char dyn[];
    __shared__ float saff[2];
    __shared__ float effb[64];
    __shared__ float red[16];
    __shared__ float cbs[64 * 8];

    const int t = threadIdx.x;
    const int wid = t >> 5;
    const int lane = t & 31;
    const int rowBase = blockIdx.y * 128;
    const int colBase = blockIdx.x * 64;

    if (t == 0) {
        if (aphase >= 0) bn_affine(aphase, bng, bnb, acnt, saff);
        else { saff[0] = 1.f; saff[1] = 0.f; }
    }
    if (FC) {
        for (int i = t; i < 64 * 8; i += NT) cbs[i] = codebook[colBase * 8 + i];
    }

    const u32 sb = (u32)__cvta_generic_to_shared(dyn);

    // loader mapping
    const int arow = t >> 1;            // 0..127
    const int brow = t >> 2;            // 0..63
    const int n_b = colBase + brow;
    const bool bv = n_b < N;

    auto issue = [&](int kt, int buf) {
        const u32 stage = sb + buf * STG;
#pragma unroll
        for (int arr = 0; arr < 2; ++arr) {
#pragma unroll
            for (int u = 0; u < 2; ++u) {
                int ch = (t & 1) * 2 + u;
                int k0 = kt + ch * 8;
                int sbv = clampi((K - k0) * 2, 0, 16);
                const void *src = sbv > 0
                    ? (const void *)(A + (size_t)arr * avs + (size_t)(rowBase + arow) * lda + k0)
                    : (const void *)A;
                cpa16(stage + arr * A_SZ + arow * ASTRB + ch * 16, src, sbv);
            }
        }
#pragma unroll
        for (int arr = 0; arr < 2; ++arr) {
            int ch = t & 3;
            int k0 = kt + ch * 8;
            int sbv = bv ? clampi((K - k0) * 2, 0, 16) : 0;
            const void *src = sbv > 0
                ? (const void *)(W + (size_t)arr * WTOT + (size_t)(bv ? n_b : 0) * ldw + k0)
                : (const void *)A;
            cpa16(stage + 2 * A_SZ + arr * B_SZ + brow * ASTRB + ch * 16, src, sbv);
        }
        cp_commitg();
    };

    float acc[2][4][4];
#pragma unroll
    for (int m = 0; m < 2; m++)
#pragma unroll
        for (int n = 0; n < 4; n++)
#pragma unroll
            for (int v = 0; v < 4; v++) acc[m][n][v] = 0.f;

    const int wr = wid >> 1;            // m block 0..3
    const int wc = wid & 1;             // n block 0..1
    const int al = lane & 15, ah = lane >> 4;
    const int b7 = lane & 7, bg = (lane >> 4) & 1, bh = (lane >> 3) & 1;

    const int T = (K + 31) >> 5;
    issue(0, 0);
    for (int it = 0; it < T; ++it) {
        cp_wait0();
        __syncthreads();
        if (it + 1 < T) issue((it + 1) * 32, (it + 1) & 1);
        const u32 stage = sb + (it & 1) * STG;
        const u32 Ab = stage;
        const u32 Bb = stage + 2 * A_SZ;
#pragma unroll
        for (int ks = 0; ks < 2; ++ks) {
            u32 a1f[2][4], a2f[2][4];
#pragma unroll
            for (int mt = 0; mt < 2; ++mt) {
                u32 ra = Ab + (wr * 32 + mt * 16 + al) * ASTRB + ks * 32 + ah * 16;
                ldsm4(a1f[mt][0], a1f[mt][1], a1f[mt][2], a1f[mt][3], ra);
                ldsm4(a2f[mt][0], a2f[mt][1], a2f[mt][2], a2f[mt][3], ra + A_SZ);
            }
            u32 b1f[4][2], b2f[4][2];
#pragma unroll
            for (int g = 0; g < 2; ++g) {
                int rrow = wc * 32 + g * 16 + bg * 8 + b7;
                u32 rb = Bb + rrow * ASTRB + ks * 32 + bh * 16;
                u32 r0, r1, r2, r3;
                ldsm4(r0, r1, r2, r3, rb);
                b1f[2 * g][0] = r0; b1f[2 * g][1] = r1;
                b1f[2 * g + 1][0] = r2; b1f[2 * g + 1][1] = r3;
                ldsm4(r0, r1, r2, r3, rb + B_SZ);
                b2f[2 * g][0] = r0; b2f[2 * g][1] = r1;
                b2f[2 * g + 1][0] = r2; b2f[2 * g + 1][1] = r3;
            }
#pragma unroll
            for (int mt = 0; mt < 2; ++mt)
#pragma unroll
                for (int nt = 0; nt < 4; ++nt) {
                    mma16816(acc[mt][nt], a1f[mt], b1f[nt]);
                    mma16816(acc[mt][nt], a1f[mt], b2f[nt]);
                    mma16816(acc[mt][nt], a2f[mt], b1f[nt]);
                }
        }
    }

    // ---- epilogue ----
    const float alpha = saff[0], beta = saff[1];
    if (t < 64) {
        int n = colBase + t;
        effb[t] = (n < N) ? (bias[n] + (wsum ? beta * wsum[n] : 0.f)) : 0.f;
    }
    __syncthreads();

    const int q = lane & 3, lr8 = lane >> 2;
    float lsum = 0.f, lsq = 0.f;
    const size_t seg = (size_t)BATCH * 512;
#pragma unroll
    for (int mt = 0; mt < 2; ++mt)
#pragma unroll
        for (int hr = 0; hr < 2; ++hr) {
            int r = rowBase + wr * 32 + mt * 16 + hr * 8 + lr8;
#pragma unroll
            for (int nt = 0; nt < 4; ++nt) {
                int ln = wc * 32 + nt * 8 + 2 * q;
                int n0 = colBase + ln;
                if (n0 >= N) continue;
                float v0 = fmaf(alpha, acc[mt][nt][hr * 2 + 0], effb[ln]);
                float v1 = fmaf(alpha, acc[mt][nt][hr * 2 + 1], effb[ln + 1]);
                if (FC) {
                    float o0 = sigf(v0);
                    float o1 = sigf(v1);
                    float q0 = -3.4e38f, q1 = -3.4e38f, m0 = 3.4e38f, m1 = 3.4e38f;
                    const float *cb0 = &cbs[ln * 8];
#pragma unroll
                    for (int e = 0; e < 8; e++) {
                        float c0 = cb0[e], c1 = cb0[8 + e];
                        float d0 = (o0 - c0) * (o0 - c0), d1 = (o1 - c1) * (o1 - c1);
                        if (d0 < m0) { m0 = d0; q0 = c0; } else if (d0 == m0) q0 = fmaxf(q0, c0);
                        if (d1 < m1) { m1 = d1; q1 = c1; } else if (d1 == m1) q1 = fmaxf(q1, c1);
                    }
                    size_t idx = (size_t)r * 512 + n0;
                    *(float2 *)(out + idx) = make_float2(o0 + (q0 - o0), o1 + (q1 - o1));
                    *(float2 *)(out + seg + idx) = make_float2(q0, q1);
                    *(float2 *)(out + 2 * seg + idx) = make_float2(o0, o1);
                } else {
                    v0 = fmaxf(v0, 0.f); v1 = fmaxf(v1, 0.f);
                    if (n0 < OUT) {
                        float m0 = mishf(v0), m1 = mishf(v1);
                        lsum += m0 + m1;
                        lsq = fmaf(m0, m0, fmaf(m1, m1, lsq));
                        sst2h(col, cvs, (size_t)r * ldc + n0, m0, m1);
                    } else {
                        sst2h(car, crvs, (size_t)r * ldcar + (n0 - OUT), v0, v1);
                    }
                }
            }
        }

    if (!FC) {
#pragma unroll
        for (int o = 16; o; o >>= 1) {
            lsum += __shfl_down_sync(0xffffffffu, lsum, o);
            lsq += __shfl_down_sync(0xffffffffu, lsq, o);
        }
        if (lane == 0) { red[wid] = lsum; red[8 + wid] = lsq; }
        __syncthreads();
        if (t == 0) {
            float s = 0.f, qq = 0.f;
#pragma unroll
            for (int w = 0; w < 8; w++) { s += red[w]; qq += red[8 + w]; }
            atomicAdd(&g_stats[sphase][0], (double)s);
            atomicAdd(&g_stats[sphase][1], (double)qq);
        }
    }
}

// ---------------- launch ----------------
extern "C" void kernel_launch(void *const *d_in, const int *in_sizes, int n_in,
                              void *d_out, int out_size) {
    (void)in_sizes; (void)n_in; (void)out_size;
    const float *x = (const float *)d_in[0];
    const float *w[9], *bb[9];
    for (int i = 0; i < 9; i++) {
        w[i] = (const float *)d_in[1 + 2 * i];
        bb[i] = (const float *)d_in[2 + 2 * i];
    }
    const float *bn_g[3] = {(const float *)d_in[19], (const float *)d_in[21], (const float *)d_in[23]};
    const float *bn_b[3] = {(const float *)d_in[20], (const float *)d_in[22], (const float *)d_in[24]};
    const float *fc_w = (const float *)d_in[25];
    const float *fc_b = (const float *)d_in[26];
    const float *cbk = (const float *)d_in[27];
    float *out = (float *)d_out;

    __half *xh, *c1, *c2, *c3, *r150, *r50, *r300, *r100, *wh;
    float *wsum;
    cudaGetSymbolAddress((void **)&xh, g_xh);
    cudaGetSymbolAddress((void **)&c1, g_c1h);
    cudaGetSymbolAddress((void **)&c2, g_c2h);
    cudaGetSymbolAddress((void **)&c3, g_c3h);
    cudaGetSymbolAddress((void **)&r150, g_r150);
    cudaGetSymbolAddress((void **)&r50, g_r50);
    cudaGetSymbolAddress((void **)&r300, g_r300);
    cudaGetSymbolAddress((void **)&r100, g_r100);
    cudaGetSymbolAddress((void **)&wh, g_wh);
    cudaGetSymbolAddress((void **)&wsum, g_ws);

    static int attr_done = 0;
    if (!attr_done) {
        cudaFuncSetAttribute(gemm_hmma<0>, cudaFuncAttributeMaxDynamicSharedMemorySize, DYN_BYTES);
        cudaFuncSetAttribute(gemm_hmma<1>, cudaFuncAttributeMaxDynamicSharedMemorySize, DYN_BYTES);
        attr_done = 1;
    }

    const size_t XS = (size_t)BATCH * 24;
    const size_t C1S = (size_t)BATCH * 304, C6S = (size_t)BATCH * 600;
    const size_t S150 = (size_t)BATCH * 152, S50 = (size_t)BATCH * 56;
    const size_t S300 = (size_t)BATCH * 304, S100 = (size_t)BATCH * 104;
    const double cnt1 = (double)BATCH * 300.0, cnt2 = (double)BATCH * 600.0;

    setup_kernel<<<1712, 128>>>(w[3], w[6], fc_w);
    splitx_kernel<<<(BATCH * 24 + 255) / 256, 256>>>(x);
    WT wt;
    wt.l[0] = {w[0], 24, 300, 24, 0};
    wt.l[1] = {w[1], 150, 150, 152, 7200};
    wt.l[2] = {w[2], 50, 50, 56, 30000};
    wt.l[3] = {w[3], 300, 600, 304, 32800};
    wt.l[4] = {w[4], 300, 300, 304, 215200};
    wt.l[5] = {w[5], 100, 100, 104, 306400};
    wt.l[6] = {w[6], 600, 600, 600, 316800};
    wt.l[7] = {w[7], 300, 300, 304, 676800};
    wt.l[8] = {w[8], 100, 100, 104, 768000};
    wt.l[9] = {fc_w, 600, 512, 600, 778400};
    splitw_kernel<<<3012, 128>>>(wt);

    auto G = [](int N) { return dim3((N + 63) / 64, BATCH / 128); };

    // phase 1: 24 -> 300(out150) -> 150(out100) -> 50(out50)
    gemm_hmma<0><<<G(300), NT, DYN_BYTES>>>(xh, XS, 24, wh + 0, 24, bb[0], nullptr,
        24, 300, 150, c1, C1S, 304, r150, S150, 152, 0, -1, nullptr, nullptr, 0.0, nullptr, nullptr);
    gemm_hmma<0><<<G(150), NT, DYN_BYTES>>>(r150, S150, 152, wh + 7200, 152, bb[1], nullptr,
        150, 150, 100, c1 + 150, C1S, 304, r50, S50, 56, 0, -1, nullptr, nullptr, 0.0, nullptr, nullptr);
    gemm_hmma<0><<<G(50), NT, DYN_BYTES>>>(r50, S50, 56, wh + 30000, 56, bb[2], nullptr,
        50, 50, 50, c1 + 250, C1S, 304, r50, S50, 56, 0, -1, nullptr, nullptr, 0.0, nullptr, nullptr);
    // phase 2 (BN1 folded)
    gemm_hmma<0><<<G(600), NT, DYN_BYTES>>>(c1, C1S, 304, wh + 32800, 304, bb[3], wsum,
        300, 600, 300, c2, C6S, 600, r300, S300, 304, 1, 0, bn_g[0], bn_b[0], cnt1, nullptr, nullptr);
    gemm_hmma<0><<<G(300), NT, DYN_BYTES>>>(r300, S300, 304, wh + 215200, 304, bb[4], nullptr,
        300, 300, 200, c2 + 300, C6S, 600, r100, S100, 104, 1, -1, nullptr, nullptr, 0.0, nullptr, nullptr);
    gemm_hmma<0><<<G(100), NT, DYN_BYTES>>>(r100, S100, 104, wh + 306400, 104, bb[5], nullptr,
        100, 100, 100, c2 + 500, C6S, 600, r100, S100, 104, 1, -1, nullptr, nullptr, 0.0, nullptr, nullptr);
    // phase 3 (BN2 folded)
    gemm_hmma<0><<<G(600), NT, DYN_BYTES>>>(c2, C6S, 600, wh + 316800, 600, bb[6], wsum + 600,
        600, 600, 300, c3, C6S, 600, r300, S300, 304, 2, 1, bn_g[1], bn_b[1], cnt2, nullptr, nullptr);
    gemm_hmma<0><<<G(300), NT, DYN_BYTES>>>(r300, S300, 304, wh + 676800, 304, bb[7], nullptr,
        300, 300, 200, c3 + 300, C6S, 600, r100, S100, 104, 2, -1, nullptr, nullptr, 0.0, nullptr, nullptr);
    gemm_hmma<0><<<G(100), NT, DYN_BYTES>>>(r100, S100, 104, wh + 768000, 104, bb[8], nullptr,
        100, 100, 100, c3 + 500, C6S, 600, r100, S100, 104, 2, -1, nullptr, nullptr, 0.0, nullptr, nullptr);
    // fc + sigmoid + codebook (BN3 folded)
    gemm_hmma<1><<<G(512), NT, DYN_BYTES>>>(c3, C6S, 600, wh + 778400, 600, fc_b, wsum + 1200,
        600, 512, 512, nullptr, 0, 0, nullptr, 0, 0, 0, 2, bn_g[2], bn_b[2], cnt2, cbk, out);
}